// round 12
// baseline (speedup 1.0000x reference)
#include <cuda_runtime.h>
#include <cuda_bf16.h>
#include <cstdint>

#define BB    2
#define TT    1024
#define HID_  1024
#define NH    16
#define DH    64
#define NCG   15
#define CHUNK 64
#define NCH   (TT/CHUNK)   // 16
#define CH2   128
#define NCH2  (TT/CH2)     // 8
#define KP    (3*HID_)
#define NQ    3200
#define QS    3200
#define LDT   40
#define BK    32
#define NSTG  5

// ---------------- device scratch ----------------
__device__ float g_qkv [BB*TT*QS];
__device__ float g_qn  [BB*TT*HID_];
__device__ float g_kn  [BB*TT*HID_];
__device__ float g_beta[BB*TT*NH];
__device__ float g_gg  [BB*TT*NH];
__device__ float g_locKK[BB*NH*NCH*DH*DH];
__device__ float g_locKV[BB*NH*NCH*DH*DH];
__device__ float g_carKK[BB*NH*NCH*DH*DH];
__device__ float g_carKV[BB*NH*NCH*DH*DH];
__device__ float g_Dsum [BB*NH*NCH];
__device__ __nv_bfloat16 g_XA2 [BB*TT*KP];
__device__ __nv_bfloat16 g_W2q [NQ*KP];
__device__ __nv_bfloat16 g_W2o [HID_*KP];
__device__ __nv_bfloat16 g_onA2[BB*TT*KP];

// ================= helpers =================
__device__ __forceinline__ uint32_t smem_u32(const void* p) {
    uint32_t a;
    asm("{ .reg .u64 t; cvta.to.shared.u64 t, %1; cvt.u32.u64 %0, t; }" : "=r"(a) : "l"(p));
    return a;
}
__device__ __forceinline__ void cpasync16(uint32_t dst, const void* src) {
    asm volatile("cp.async.ca.shared.global [%0], [%1], 16;" :: "r"(dst), "l"(src));
}
__device__ __forceinline__ void ldsm4(uint32_t& r0, uint32_t& r1, uint32_t& r2, uint32_t& r3, uint32_t addr) {
    asm volatile("ldmatrix.sync.aligned.m8n8.x4.shared.b16 {%0,%1,%2,%3}, [%4];"
                 : "=r"(r0), "=r"(r1), "=r"(r2), "=r"(r3) : "r"(addr));
}
__device__ __forceinline__ void mma16816(float* c, uint32_t a0, uint32_t a1, uint32_t a2, uint32_t a3,
                                         uint32_t b0, uint32_t b1) {
    asm volatile("mma.sync.aligned.m16n8k16.row.col.f32.bf16.bf16.f32 "
                 "{%0,%1,%2,%3}, {%4,%5,%6,%7}, {%8,%9}, {%0,%1,%2,%3};"
                 : "+f"(c[0]), "+f"(c[1]), "+f"(c[2]), "+f"(c[3])
                 : "r"(a0), "r"(a1), "r"(a2), "r"(a3), "r"(b0), "r"(b1));
}

// ================= HMMA GEMM: 8 warps 64x32, 5-stage cp.async, 1 sync/stage =================
// dyn smem: NSTG * 20480 = 102400 B. 256 threads.
__global__ __launch_bounds__(256, 2) void mma_gemm(const __nv_bfloat16* __restrict__ A,
                                                   const __nv_bfloat16* __restrict__ B,
                                                   float* __restrict__ C, int N) {
    extern __shared__ __align__(16) char dsm[];
    uint32_t smbase = smem_u32(dsm);
    int tid = threadIdx.x, lane = tid & 31, wid = tid >> 5;
    int wrow = wid >> 2, wcol = wid & 3;
    int bm = blockIdx.y * 128, bn = blockIdx.x * 128;
    const __nv_bfloat16* Ap = A + (size_t)bm * KP;
    const __nv_bfloat16* Bp = B + (size_t)bn * KP;

    float acc[16][4];
#pragma unroll
    for (int i = 0; i < 16; i++)
#pragma unroll
        for (int j = 0; j < 4; j++) acc[i][j] = 0.f;

    int li0r = tid >> 2, li0c = (tid & 3) << 3;
    int li1r = (tid + 256) >> 2, li1c = li0c;

    auto issue = [&](int s) {
        int buf = s % NSTG;
        int kb = s * BK;
        uint32_t ab = smbase + buf * 20480;
        cpasync16(ab + li0r * 80 + li0c * 2, Ap + (size_t)li0r * KP + kb + li0c);
        cpasync16(ab + li1r * 80 + li1c * 2, Ap + (size_t)li1r * KP + kb + li1c);
        uint32_t bb2 = ab + 10240;
        cpasync16(bb2 + li0r * 80 + li0c * 2, Bp + (size_t)li0r * KP + kb + li0c);
        cpasync16(bb2 + li1r * 80 + li1c * 2, Bp + (size_t)li1r * KP + kb + li1c);
        asm volatile("cp.async.commit_group;");
    };

    const int nk = KP / BK;  // 96
    issue(0); issue(1); issue(2); issue(3);

    int bgrp = lane >> 3, brow = lane & 7;
    int bn_off = ((bgrp & 2) ? 8 : 0) + brow;
    int bk_off = (bgrp & 1) ? 8 : 0;

    for (int k = 0; k < nk; k++) {
        if (k + 4 < nk) asm volatile("cp.async.wait_group 3;");
        else            asm volatile("cp.async.wait_group 0;");
        __syncthreads();
        if (k + 4 < nk) issue(k + 4);

        int buf = k % NSTG;
        uint32_t abase = smbase + buf * 20480;
        uint32_t bbase = abase + 10240;
#pragma unroll
        for (int ks = 0; ks < 2; ks++) {
            uint32_t a[4][4];
#pragma unroll
            for (int mt = 0; mt < 4; mt++) {
                int row = wrow * 64 + mt * 16 + (lane & 15);
                int col = ks * 16 + (lane >> 4) * 8;
                ldsm4(a[mt][0], a[mt][1], a[mt][2], a[mt][3], abase + (row * LDT + col) * 2);
            }
            uint32_t bf[2][4];
#pragma unroll
            for (int ntp = 0; ntp < 2; ntp++) {
                int n = wcol * 32 + ntp * 16 + bn_off;
                int kk = ks * 16 + bk_off;
                ldsm4(bf[ntp][0], bf[ntp][1], bf[ntp][2], bf[ntp][3], bbase + (n * LDT + kk) * 2);
            }
#pragma unroll
            for (int mt = 0; mt < 4; mt++)
#pragma unroll
                for (int ntp = 0; ntp < 2; ntp++) {
                    mma16816(acc[mt * 4 + 2 * ntp],
                             a[mt][0], a[mt][1], a[mt][2], a[mt][3], bf[ntp][0], bf[ntp][1]);
                    mma16816(acc[mt * 4 + 2 * ntp + 1],
                             a[mt][0], a[mt][1], a[mt][2], a[mt][3], bf[ntp][2], bf[ntp][3]);
                }
        }
    }

#pragma unroll
    for (int mt = 0; mt < 4; mt++) {
#pragma unroll
        for (int nt = 0; nt < 4; nt++) {
            float* c = acc[mt * 4 + nt];
            int row = bm + wrow * 64 + mt * 16 + (lane >> 2);
            int col = bn + wcol * 32 + nt * 8 + (lane & 3) * 2;
            *(float2*)&C[(size_t)row * N + col] = make_float2(c[0], c[1]);
            *(float2*)&C[(size_t)(row + 8) * N + col] = make_float2(c[2], c[3]);
        }
    }
}

// ================= split X into [hi | lo | hi] =================
__global__ __launch_bounds__(256) void splitX(const float* __restrict__ X,
                                              __nv_bfloat16* __restrict__ A2) {
    int i = blockIdx.x * 256 + threadIdx.x;
    int row = i >> 10, k = i & 1023;
    float v = X[i];
    __nv_bfloat16 h = __float2bfloat16(v);
    __nv_bfloat16 l = __float2bfloat16(v - __bfloat162float(h));
    size_t base = (size_t)row * KP;
    A2[base + k] = h;
    A2[base + HID_ + k] = l;
    A2[base + 2 * HID_ + k] = h;
}

// ================= transpose + split weights =================
__global__ __launch_bounds__(256) void transW(const float* __restrict__ W0,
                                              const float* __restrict__ W1,
                                              const float* __restrict__ W2,
                                              __nv_bfloat16* __restrict__ B2) {
    __shared__ float ts[32][33];
    int nt = blockIdx.x, kt = blockIdx.y;
    int tx = threadIdx.x & 31, ty = threadIdx.x >> 5;
    int n0 = nt * 32, k0 = kt * 32;
    const float* W = (n0 < 1024) ? W0 : ((n0 < 2048) ? W1 : W2);
    int nc = n0 & 1023;
#pragma unroll
    for (int i = 0; i < 32; i += 8)
        ts[ty + i][tx] = W[(size_t)(k0 + ty + i) * 1024 + nc + tx];
    __syncthreads();
#pragma unroll
    for (int i = 0; i < 32; i += 8) {
        int n = n0 + ty + i, k = k0 + tx;
        float v = ts[tx][ty + i];
        __nv_bfloat16 h = __float2bfloat16(v);
        __nv_bfloat16 l = __float2bfloat16(v - __bfloat162float(h));
        size_t base = (size_t)n * KP;
        B2[base + k] = h;
        B2[base + HID_ + k] = h;
        B2[base + 2 * HID_ + k] = l;
    }
}

// ================= Wa/Wb into GEMM rows 3072..3103 =================
__global__ __launch_bounds__(256) void transAB(const float* __restrict__ Wa,
                                               const float* __restrict__ Wb,
                                               __nv_bfloat16* __restrict__ B2) {
    int n = blockIdx.x;
    const float* W = (n < 16) ? Wa : Wb;
    int h = n & 15;
    size_t base = (size_t)(3072 + n) * KP;
    for (int k = threadIdx.x; k < HID_; k += 256) {
        float v = W[(size_t)k * NH + h];
        __nv_bfloat16 hh = __float2bfloat16(v);
        __nv_bfloat16 ll = __float2bfloat16(v - __bfloat162float(hh));
        B2[base + k] = hh;
        B2[base + HID_ + k] = hh;
        B2[base + 2 * HID_ + k] = ll;
    }
}

// ================= beta/g epilogue =================
__global__ __launch_bounds__(256) void abpost(const float* __restrict__ C,
                                              const float* __restrict__ bb,
                                              const float* __restrict__ A_log,
                                              const float* __restrict__ dt_bias,
                                              float* __restrict__ beta_o,
                                              float* __restrict__ g_o) {
    int i = blockIdx.x * 256 + threadIdx.x;
    int row = i >> 4, h = i & 15;
    float sa = C[(size_t)row * QS + 3072 + h];
    float sb = C[(size_t)row * QS + 3088 + h];
    float bv = 1.f / (1.f + expf(-(sb + bb[h])));
    float av = sa + dt_bias[h];
    float sp = (av > 20.f) ? av : log1pf(expf(av));
    beta_o[(size_t)row * NH + h] = bv;
    g_o[(size_t)row * NH + h] = -expf(A_log[h]) * sp;
}

// ================= merged conv + silu + per-head l2norm =================
__global__ __launch_bounds__(1024) void conv2_kernel(const float* __restrict__ xin,
                                                     const float* __restrict__ wq,
                                                     const float* __restrict__ wk,
                                                     float* __restrict__ qn,
                                                     float* __restrict__ kn) {
    int which = blockIdx.y;
    const float* wconv = which ? wk : wq;
    float* xout = which ? kn : qn;
    int off = which ? HID_ : 0;
    int bt = blockIdx.x;
    int b = bt >> 10;
    int t = bt & (TT - 1);
    int c = threadIdx.x;
    float4 w4 = *(const float4*)&wconv[c * 4];
    const float* xp = xin + (size_t)b * TT * QS + off + c;
    float acc = 0.f;
    if (t >= 3) acc += xp[(size_t)(t - 3) * QS] * w4.x;
    if (t >= 2) acc += xp[(size_t)(t - 2) * QS] * w4.y;
    if (t >= 1) acc += xp[(size_t)(t - 1) * QS] * w4.z;
    acc += xp[(size_t)t * QS] * w4.w;
    float y = acc / (1.f + expf(-acc));
    __shared__ float wsum[32];
    float ss = y * y;
#pragma unroll
    for (int o = 16; o > 0; o >>= 1) ss += __shfl_xor_sync(0xffffffffu, ss, o);
    if ((c & 31) == 0) wsum[c >> 5] = ss;
    __syncthreads();
    float tot = wsum[(c >> 6) * 2] + wsum[(c >> 6) * 2 + 1];
    xout[(size_t)bt * HID_ + c] = y * rsqrtf(tot + 1e-6f);
}

// ================= pass1: per-chunk(64) local state sums =================
__global__ __launch_bounds__(256) void pass1_kernel(const float* __restrict__ kn,
                                                    const float* __restrict__ qkv,
                                                    const float* __restrict__ gg,
                                                    const float* __restrict__ bet) {
    __shared__ __align__(16) float kc[CHUNK * 64];
    __shared__ __align__(16) float vc[CHUNK * 64];
    __shared__ float ds[CHUNK], ws[CHUNK], gs[CHUNK];
    int blk = blockIdx.x;
    int bh = blk >> 4, c = blk & 15;
    int b = bh >> 4, h = bh & (NH - 1);
    int tid = threadIdx.x;
    int j = tid & 63, rg = tid >> 6;
    size_t rowbase = (size_t)b * TT + c * CHUNK;
    for (int l4 = tid; l4 < CHUNK * 16; l4 += 256) {
        int t = l4 >> 4, d4 = (l4 & 15) << 2;
        *(float4*)&kc[t * 64 + d4] = *(const float4*)&kn[(rowbase + t) * HID_ + h * DH + d4];
        *(float4*)&vc[t * 64 + d4] = *(const float4*)&qkv[(rowbase + t) * QS + 2048 + h * DH + d4];
    }
    if (tid < CHUNK) {
        float g = gg[(rowbase + tid) * NH + h];
        gs[tid] = g;
        ds[tid] = expf(g);
        ws[tid] = bet[(rowbase + tid) * NH + h];
    }
    __syncthreads();
    if (tid == 0) {
        float s = 0.f;
        for (int t = 0; t < CHUNK; t++) s += gs[t];
        g_Dsum[blk] = s;
    }
    float hkk[16], hkv[16];
#pragma unroll
    for (int ii = 0; ii < 16; ii++) { hkk[ii] = 0.f; hkv[ii] = 0.f; }
    for (int t = 0; t < CHUNK; t++) {
        float d = ds[t], w = ws[t];
        float a = w * kc[t * 64 + j];
        float bf = w * vc[t * 64 + j];
        const float4* k4 = (const float4*)&kc[t * 64 + rg * 16];
#pragma unroll
        for (int q = 0; q < 4; q++) {
            float4 kv = k4[q];
            hkk[4*q+0] = d * hkk[4*q+0] + a * kv.x;
            hkk[4*q+1] = d * hkk[4*q+1] + a * kv.y;
            hkk[4*q+2] = d * hkk[4*q+2] + a * kv.z;
            hkk[4*q+3] = d * hkk[4*q+3] + a * kv.w;
            hkv[4*q+0] = d * hkv[4*q+0] + bf * kv.x;
            hkv[4*q+1] = d * hkv[4*q+1] + bf * kv.y;
            hkv[4*q+2] = d * hkv[4*q+2] + bf * kv.z;
            hkv[4*q+3] = d * hkv[4*q+3] + bf * kv.w;
        }
    }
    size_t base = (size_t)blk * 4096;
#pragma unroll
    for (int ii = 0; ii < 16; ii++) {
        g_locKK[base + (rg * 16 + ii) * 64 + j] = hkk[ii];
        g_locKV[base + (rg * 16 + ii) * 64 + j] = hkv[ii];
    }
}

// ================= pass2: per-element chunk-carry scan (even-chunk stores only) =================
__global__ __launch_bounds__(256) void pass2b_kernel() {
    int bh = blockIdx.x >> 4;
    int idx = (blockIdx.x & 15) * 256 + threadIdx.x;
    float cK = 0.f, cV = 0.f;
#pragma unroll
    for (int c = 0; c < NCH; c++) {
        size_t base = ((size_t)bh * NCH + c) * 4096 + idx;
        if ((c & 1) == 0) {
            g_carKK[base] = cK;
            g_carKV[base] = cV;
        }
        float D = expf(g_Dsum[bh * NCH + c]);
        cK = D * cK + g_locKK[base];
        cV = D * cV + g_locKV[base];
    }
}

// ================= fused2: parity-split dual-pipeline CG over 128-step chunks (R10 version) =================
__global__ __launch_bounds__(256, 2) void fused2_kernel(const float* __restrict__ kn,
                                                        const float* __restrict__ qn,
                                                        const float* __restrict__ qkv,
                                                        const float* __restrict__ gg,
                                                        const float* __restrict__ bet,
                                                        const float* __restrict__ lambda_p,
                                                        const float* __restrict__ norm_w,
                                                        __nv_bfloat16* __restrict__ onA2) {
    __shared__ __align__(16) float kc[CH2 * 64];
    __shared__ float ds[CH2], ws[CH2];
    __shared__ float lams[64], nws[64];
    __shared__ __align__(16) float rsh[2][64];
    __shared__ float red[2][128];
    __shared__ float wu[2][4], wv[2][4];

    int blk = blockIdx.x;
    int bh = blk >> 3, c = blk & 7;
    int b = bh >> 4, h = bh & (NH - 1);
    int tid = threadIdx.x;
    int g = tid >> 7;
    int tg = tid & 127;
    int j = tg & 63, rg = tg >> 6;
    int wig = tg >> 5;
    size_t rowbase = (size_t)b * TT + c * CH2;

    for (int l4 = tid; l4 < CH2 * 16; l4 += 256) {
        int t = l4 >> 4, d4 = (l4 & 15) << 2;
        *(float4*)&kc[t * 64 + d4] = *(const float4*)&kn[(rowbase + t) * HID_ + h * DH + d4];
    }
    if (tid < CH2) {
        ds[tid] = expf(gg[(rowbase + tid) * NH + h]);
        ws[tid] = bet[(rowbase + tid) * NH + h];
    }
    if (tid >= 128 && tid < 192) {
        int jj = tid - 128;
        float lp = lambda_p[h * DH + jj];
        lams[jj] = ((lp > 20.f) ? lp : log1pf(expf(lp))) + 0.25f;
        nws[jj] = norm_w[jj];
    }
    float hkk[32], hkv[32];
    {
        const float* cK = g_carKK + ((size_t)bh * NCH + 2 * c) * 4096;
        const float* cV = g_carKV + ((size_t)bh * NCH + 2 * c) * 4096;
#pragma unroll
        for (int ii = 0; ii < 32; ii++) {
            hkk[ii] = cK[(rg * 32 + ii) * 64 + j];
            hkv[ii] = cV[(rg * 32 + ii) * 64 + j];
        }
    }
    __syncthreads();
    float lam = lams[j];
    float nw = nws[j];

    const float* vbase = qkv + 2048 + h * DH + j;
    const float* qbase = qn + h * DH + j;

    float pv0 = (g == 1) ? vbase[(rowbase + 0) * QS] : 0.f;
    float pv1 = vbase[(rowbase + g) * QS];
    float pq  = qbase[(rowbase + g) * HID_];

    for (int s = 0; s < CH2 / 2; s++) {
        int tt = 2 * s + g;
        float v0 = pv0, v1 = pv1, rhs = pq;
        if (s + 1 < CH2 / 2) {
            int tn = tt + 2;
            pv0 = vbase[(rowbase + tn - 1) * QS];
            pv1 = vbase[(rowbase + tn) * QS];
            pq  = qbase[(rowbase + tn) * HID_];
        }
        if (s > 0 || g == 1) {
            int t = tt - 1;
            float d = ds[t], w = ws[t];
            float a = w * kc[t * 64 + j];
            float bf = w * v0;
            const float4* k4 = (const float4*)&kc[t * 64 + rg * 32];
#pragma unroll
            for (int q = 0; q < 8; q++) {
                float4 kv = k4[q];
                hkk[4*q+0] = d * hkk[4*q+0] + a * kv.x;
                hkk[4*q+1] = d * hkk[4*q+1] + a * kv.y;
                hkk[4*q+2] = d * hkk[4*q+2] + a * kv.z;
                hkk[4*q+3] = d * hkk[4*q+3] + a * kv.w;
                hkv[4*q+0] = d * hkv[4*q+0] + bf * kv.x;
                hkv[4*q+1] = d * hkv[4*q+1] + bf * kv.y;
                hkv[4*q+2] = d * hkv[4*q+2] + bf * kv.z;
                hkv[4*q+3] = d * hkv[4*q+3] + bf * kv.w;
            }
        }
        {
            int t = tt;
            float d = ds[t], w = ws[t];
            float a = w * kc[t * 64 + j];
            float bf = w * v1;
            const float4* k4 = (const float4*)&kc[t * 64 + rg * 32];
#pragma unroll
            for (int q = 0; q < 8; q++) {
                float4 kv = k4[q];
                hkk[4*q+0] = d * hkk[4*q+0] + a * kv.x;
                hkk[4*q+1] = d * hkk[4*q+1] + a * kv.y;
                hkk[4*q+2] = d * hkk[4*q+2] + a * kv.z;
                hkk[4*q+3] = d * hkk[4*q+3] + a * kv.w;
                hkv[4*q+0] = d * hkv[4*q+0] + bf * kv.x;
                hkv[4*q+1] = d * hkv[4*q+1] + bf * kv.y;
                hkv[4*q+2] = d * hkv[4*q+2] + bf * kv.z;
                hkv[4*q+3] = d * hkv[4*q+3] + bf * kv.w;
            }
        }
        float r = rhs;
        float x = 0.f, p = 0.f, sv = 0.f;
        float mu_prev = 1.f, alpha_prev = 1.f;
        if (rg == 0) rsh[g][j] = r;
        for (int it = 0; it < NCG; it++) {
            __syncthreads();
            const float4* r4 = (const float4*)&rsh[g][rg * 32];
            float spart = 0.f;
#pragma unroll
            for (int q = 0; q < 8; q++) {
                float4 rv = r4[q];
                spart += hkk[4*q+0]*rv.x + hkk[4*q+1]*rv.y + hkk[4*q+2]*rv.z + hkk[4*q+3]*rv.w;
            }
            red[g][rg * 64 + j] = spart;
            float rr = r * r;
            float u = 0.5f * rr;
            float v = r * spart + 0.5f * lam * rr;
#pragma unroll
            for (int o = 16; o > 0; o >>= 1) {
                u += __shfl_xor_sync(0xffffffffu, u, o);
                v += __shfl_xor_sync(0xffffffffu, v, o);
            }
            if ((tg & 31) == 0) { wu[g][wig] = u; wv[g][wig] = v; }
            __syncthreads();
            float mu = (wu[g][0] + wu[g][1]) + (wu[g][2] + wu[g][3]);
            float dl = (wv[g][0] + wv[g][1]) + (wv[g][2] + wv[g][3]);
            float Ap = lam * r + red[g][j] + red[g][64 + j];
            float beta = (it == 0) ? 0.f : mu / (mu_prev + 1e-12f);
            float alpha = mu / ((dl - beta * mu / alpha_prev) + 1e-12f);
            p = r + beta * p;
            sv = Ap + beta * sv;
            x += alpha * p;
            mu_prev = mu; alpha_prev = alpha;
            if (it < NCG - 1) {
                r -= alpha * sv;
                if (rg == 0) rsh[g][j] = r;
            }
        }
        __syncthreads();
        if (rg == 0) rsh[g][j] = x;
        __syncthreads();
        {
            const float4* x4 = (const float4*)&rsh[g][rg * 32];
            float opart = 0.f;
#pragma unroll
            for (int q = 0; q < 8; q++) {
                float4 xv = x4[q];
                opart += hkv[4*q+0]*xv.x + hkv[4*q+1]*xv.y + hkv[4*q+2]*xv.z + hkv[4*q+3]*xv.w;
            }
            red[g][rg * 64 + j] = opart;
        }
        __syncthreads();
        float o = red[g][j] + red[g][64 + j];
        float u2 = 0.5f * o * o;
#pragma unroll
        for (int oo = 16; oo > 0; oo >>= 1) u2 += __shfl_xor_sync(0xffffffffu, u2, oo);
        if ((tg & 31) == 0) wu[g][wig] = u2;
        __syncthreads();
        float ssum = (wu[g][0] + wu[g][1]) + (wu[g][2] + wu[g][3]);
        if (rg == 0) {
            float on = o * rsqrtf(ssum * (1.f / 64.f) + 1e-5f) * nw;
            __nv_bfloat16 hi = __float2bfloat16(on);
            __nv_bfloat16 lo = __float2bfloat16(on - __bfloat162float(hi));
            size_t base2 = (rowbase + tt) * KP + h * DH + j;
            onA2[base2] = hi;
            onA2[base2 + HID_] = lo;
            onA2[base2 + 2 * HID_] = hi;
        }
        __syncthreads();
    }
}

// ================= host launcher =================
extern "C" void kernel_launch(void* const* d_in, const int* in_sizes, int n_in,
                              void* d_out, int out_size) {
    const float* X        = (const float*)d_in[0];
    const float* Wq       = (const float*)d_in[1];
    const float* Wk       = (const float*)d_in[2];
    const float* Wv       = (const float*)d_in[3];
    const float* Wa       = (const float*)d_in[4];
    const float* Wb       = (const float*)d_in[5];
    const float* bb       = (const float*)d_in[6];
    const float* A_log    = (const float*)d_in[7];
    const float* dt_bias  = (const float*)d_in[8];
    const float* lambda_p = (const float*)d_in[9];
    const float* Wconv_q  = (const float*)d_in[10];
    const float* Wconv_k  = (const float*)d_in[11];
    const float* norm_w   = (const float*)d_in[12];
    const float* Wo       = (const float*)d_in[13];

    float *qkv, *qn, *kn, *beta, *gdec;
    __nv_bfloat16 *XA2, *W2q, *W2o, *onA2;
    cudaGetSymbolAddress((void**)&qkv,  g_qkv);
    cudaGetSymbolAddress((void**)&qn,   g_qn);
    cudaGetSymbolAddress((void**)&kn,   g_kn);
    cudaGetSymbolAddress((void**)&beta, g_beta);
    cudaGetSymbolAddress((void**)&gdec, g_gg);
    cudaGetSymbolAddress((void**)&XA2,  g_XA2);
    cudaGetSymbolAddress((void**)&W2q,  g_W2q);
    cudaGetSymbolAddress((void**)&W2o,  g_W2o);
    cudaGetSymbolAddress((void**)&onA2, g_onA2);

    const int MMA_SMEM = NSTG * 20480;   // 102400
    cudaFuncSetAttribute(mma_gemm, cudaFuncAttributeMaxDynamicSharedMemorySize, MMA_SMEM);

    const int M = BB * TT;

    splitX<<<(M * HID_) / 256, 256>>>(X, XA2);                             // 1
    transW<<<dim3(96, 32), 256>>>(Wq, Wk, Wv, W2q);                        // 2
    transAB<<<32, 256>>>(Wa, Wb, W2q);                                     // 3
    mma_gemm<<<dim3(NQ / 128, 16), 256, MMA_SMEM>>>(XA2, W2q, qkv, NQ);    // 4 <- profiled
    transW<<<dim3(32, 32), 256>>>(Wo, Wo, Wo, W2o);                        // 5
    abpost<<<(M * NH) / 256, 256>>>(qkv, bb, A_log, dt_bias, beta, gdec);
    conv2_kernel<<<dim3(M, 2), 1024>>>(qkv, Wconv_q, Wconv_k, qn, kn);
    pass1_kernel<<<BB * NH * NCH, 256>>>(kn, qkv, gdec, beta);
    pass2b_kernel<<<BB * NH * 16, 256>>>();
    fused2_kernel<<<BB * NH * NCH2, 256>>>(kn, qn, qkv, gdec, beta, lambda_p, norm_w, onA2);
    mma_gemm<<<dim3(8, 16), 256, MMA_SMEM>>>(onA2, W2o, (float*)d_out, HID_);
}

// round 13
// speedup vs baseline: 1.6740x; 1.6740x over previous
#include <cuda_runtime.h>
#include <cuda_bf16.h>
#include <cstdint>

#define BB    2
#define TT    1024
#define HID_  1024
#define NH    16
#define DH    64
#define NCG   15
#define CHUNK 64
#define NCH   (TT/CHUNK)   // 16
#define CH2   128
#define NCH2  (TT/CH2)     // 8
#define KP    (3*HID_)
#define NQ    3200
#define QS    3200
#define LDT   40
#define BK    32
#define NSTG  4

// ---------------- device scratch ----------------
__device__ float g_qkv [BB*TT*QS];
__device__ float g_qn  [BB*TT*HID_];
__device__ float g_kn  [BB*TT*HID_];
__device__ float g_beta[BB*TT*NH];
__device__ float g_gg  [BB*TT*NH];
__device__ float g_locKK[BB*NH*NCH*DH*DH];
__device__ float g_locKV[BB*NH*NCH*DH*DH];
__device__ float g_carKK[BB*NH*NCH*DH*DH];
__device__ float g_carKV[BB*NH*NCH*DH*DH];
__device__ float g_Dsum [BB*NH*NCH];
__device__ __nv_bfloat16 g_XA2 [BB*TT*KP];
__device__ __nv_bfloat16 g_W2q [NQ*KP];
__device__ __nv_bfloat16 g_W2o [HID_*KP];
__device__ __nv_bfloat16 g_onA2[BB*TT*KP];

// ================= helpers =================
__device__ __forceinline__ uint32_t smem_u32(const void* p) {
    uint32_t a;
    asm("{ .reg .u64 t; cvta.to.shared.u64 t, %1; cvt.u32.u64 %0, t; }" : "=r"(a) : "l"(p));
    return a;
}
__device__ __forceinline__ void cpasync16(uint32_t dst, const void* src) {
    asm volatile("cp.async.ca.shared.global [%0], [%1], 16;" :: "r"(dst), "l"(src));
}
__device__ __forceinline__ void ldsm4(uint32_t& r0, uint32_t& r1, uint32_t& r2, uint32_t& r3, uint32_t addr) {
    asm volatile("ldmatrix.sync.aligned.m8n8.x4.shared.b16 {%0,%1,%2,%3}, [%4];"
                 : "=r"(r0), "=r"(r1), "=r"(r2), "=r"(r3) : "r"(addr));
}
__device__ __forceinline__ void mma16816(float* c, uint32_t a0, uint32_t a1, uint32_t a2, uint32_t a3,
                                         uint32_t b0, uint32_t b1) {
    asm volatile("mma.sync.aligned.m16n8k16.row.col.f32.bf16.bf16.f32 "
                 "{%0,%1,%2,%3}, {%4,%5,%6,%7}, {%8,%9}, {%0,%1,%2,%3};"
                 : "+f"(c[0]), "+f"(c[1]), "+f"(c[2]), "+f"(c[3])
                 : "r"(a0), "r"(a1), "r"(a2), "r"(a3), "r"(b0), "r"(b1));
}

// ================= HMMA GEMM: 8 warps 64x32, 4-stage cp.async, 1 sync/stage (R10 config) =================
__global__ __launch_bounds__(256, 2) void mma_gemm(const __nv_bfloat16* __restrict__ A,
                                                   const __nv_bfloat16* __restrict__ B,
                                                   float* __restrict__ C, int N) {
    extern __shared__ __align__(16) char dsm[];
    uint32_t smbase = smem_u32(dsm);
    int tid = threadIdx.x, lane = tid & 31, wid = tid >> 5;
    int wrow = wid >> 2, wcol = wid & 3;
    int bm = blockIdx.y * 128, bn = blockIdx.x * 128;
    const __nv_bfloat16* Ap = A + (size_t)bm * KP;
    const __nv_bfloat16* Bp = B + (size_t)bn * KP;

    float acc[16][4];
#pragma unroll
    for (int i = 0; i < 16; i++)
#pragma unroll
        for (int j = 0; j < 4; j++) acc[i][j] = 0.f;

    int li0r = tid >> 2, li0c = (tid & 3) << 3;
    int li1r = (tid + 256) >> 2, li1c = li0c;

    auto issue = [&](int s) {
        int buf = s & (NSTG - 1);
        int kb = s * BK;
        uint32_t ab = smbase + buf * 20480;
        cpasync16(ab + li0r * 80 + li0c * 2, Ap + (size_t)li0r * KP + kb + li0c);
        cpasync16(ab + li1r * 80 + li1c * 2, Ap + (size_t)li1r * KP + kb + li1c);
        uint32_t bb2 = ab + 10240;
        cpasync16(bb2 + li0r * 80 + li0c * 2, Bp + (size_t)li0r * KP + kb + li0c);
        cpasync16(bb2 + li1r * 80 + li1c * 2, Bp + (size_t)li1r * KP + kb + li1c);
        asm volatile("cp.async.commit_group;");
    };

    const int nk = KP / BK;  // 96
    issue(0); issue(1); issue(2);

    int bgrp = lane >> 3, brow = lane & 7;
    int bn_off = ((bgrp & 2) ? 8 : 0) + brow;
    int bk_off = (bgrp & 1) ? 8 : 0;

    for (int k = 0; k < nk; k++) {
        if (k + 3 < nk) asm volatile("cp.async.wait_group 2;");
        else            asm volatile("cp.async.wait_group 0;");
        __syncthreads();
        if (k + 3 < nk) issue(k + 3);

        int buf = k & (NSTG - 1);
        uint32_t abase = smbase + buf * 20480;
        uint32_t bbase = abase + 10240;
#pragma unroll
        for (int ks = 0; ks < 2; ks++) {
            uint32_t a[4][4];
#pragma unroll
            for (int mt = 0; mt < 4; mt++) {
                int row = wrow * 64 + mt * 16 + (lane & 15);
                int col = ks * 16 + (lane >> 4) * 8;
                ldsm4(a[mt][0], a[mt][1], a[mt][2], a[mt][3], abase + (row * LDT + col) * 2);
            }
            uint32_t bf[2][4];
#pragma unroll
            for (int ntp = 0; ntp < 2; ntp++) {
                int n = wcol * 32 + ntp * 16 + bn_off;
                int kk = ks * 16 + bk_off;
                ldsm4(bf[ntp][0], bf[ntp][1], bf[ntp][2], bf[ntp][3], bbase + (n * LDT + kk) * 2);
            }
#pragma unroll
            for (int mt = 0; mt < 4; mt++)
#pragma unroll
                for (int ntp = 0; ntp < 2; ntp++) {
                    mma16816(acc[mt * 4 + 2 * ntp],
                             a[mt][0], a[mt][1], a[mt][2], a[mt][3], bf[ntp][0], bf[ntp][1]);
                    mma16816(acc[mt * 4 + 2 * ntp + 1],
                             a[mt][0], a[mt][1], a[mt][2], a[mt][3], bf[ntp][2], bf[ntp][3]);
                }
        }
    }

#pragma unroll
    for (int mt = 0; mt < 4; mt++) {
#pragma unroll
        for (int nt = 0; nt < 4; nt++) {
            float* c = acc[mt * 4 + nt];
            int row = bm + wrow * 64 + mt * 16 + (lane >> 2);
            int col = bn + wcol * 32 + nt * 8 + (lane & 3) * 2;
            *(float2*)&C[(size_t)row * N + col] = make_float2(c[0], c[1]);
            *(float2*)&C[(size_t)(row + 8) * N + col] = make_float2(c[2], c[3]);
        }
    }
}

// ================= split X into [hi | lo | hi] =================
__global__ __launch_bounds__(256) void splitX(const float* __restrict__ X,
                                              __nv_bfloat16* __restrict__ A2) {
    int i = blockIdx.x * 256 + threadIdx.x;
    int row = i >> 10, k = i & 1023;
    float v = X[i];
    __nv_bfloat16 h = __float2bfloat16(v);
    __nv_bfloat16 l = __float2bfloat16(v - __bfloat162float(h));
    size_t base = (size_t)row * KP;
    A2[base + k] = h;
    A2[base + HID_ + k] = l;
    A2[base + 2 * HID_ + k] = h;
}

// ================= transpose + split weights =================
__global__ __launch_bounds__(256) void transW(const float* __restrict__ W0,
                                              const float* __restrict__ W1,
                                              const float* __restrict__ W2,
                                              __nv_bfloat16* __restrict__ B2) {
    __shared__ float ts[32][33];
    int nt = blockIdx.x, kt = blockIdx.y;
    int tx = threadIdx.x & 31, ty = threadIdx.x >> 5;
    int n0 = nt * 32, k0 = kt * 32;
    const float* W = (n0 < 1024) ? W0 : ((n0 < 2048) ? W1 : W2);
    int nc = n0 & 1023;
#pragma unroll
    for (int i = 0; i < 32; i += 8)
        ts[ty + i][tx] = W[(size_t)(k0 + ty + i) * 1024 + nc + tx];
    __syncthreads();
#pragma unroll
    for (int i = 0; i < 32; i += 8) {
        int n = n0 + ty + i, k = k0 + tx;
        float v = ts[tx][ty + i];
        __nv_bfloat16 h = __float2bfloat16(v);
        __nv_bfloat16 l = __float2bfloat16(v - __bfloat162float(h));
        size_t base = (size_t)n * KP;
        B2[base + k] = h;
        B2[base + HID_ + k] = h;
        B2[base + 2 * HID_ + k] = l;
    }
}

// ================= Wa/Wb into GEMM rows 3072..3103 (8 blocks x 4 rows) =================
__global__ __launch_bounds__(256) void transAB(const float* __restrict__ Wa,
                                               const float* __restrict__ Wb,
                                               __nv_bfloat16* __restrict__ B2) {
    int n = blockIdx.x * 4 + (threadIdx.x >> 6);   // 0..31
    int t64 = threadIdx.x & 63;
    const float* W = (n < 16) ? Wa : Wb;
    int h = n & 15;
    size_t base = (size_t)(3072 + n) * KP;
    for (int k = t64; k < HID_; k += 64) {
        float v = W[(size_t)k * NH + h];
        __nv_bfloat16 hh = __float2bfloat16(v);
        __nv_bfloat16 ll = __float2bfloat16(v - __bfloat162float(hh));
        B2[base + k] = hh;
        B2[base + HID_ + k] = hh;
        B2[base + 2 * HID_ + k] = ll;
    }
}

// ================= beta/g epilogue =================
__global__ __launch_bounds__(256) void abpost(const float* __restrict__ C,
                                              const float* __restrict__ bb,
                                              const float* __restrict__ A_log,
                                              const float* __restrict__ dt_bias,
                                              float* __restrict__ beta_o,
                                              float* __restrict__ g_o) {
    int i = blockIdx.x * 256 + threadIdx.x;
    int row = i >> 4, h = i & 15;
    float sa = C[(size_t)row * QS + 3072 + h];
    float sb = C[(size_t)row * QS + 3088 + h];
    float bv = 1.f / (1.f + expf(-(sb + bb[h])));
    float av = sa + dt_bias[h];
    float sp = (av > 20.f) ? av : log1pf(expf(av));
    beta_o[(size_t)row * NH + h] = bv;
    g_o[(size_t)row * NH + h] = -expf(A_log[h]) * sp;
}

// ================= merged conv + silu + per-head l2norm =================
__global__ __launch_bounds__(1024) void conv2_kernel(const float* __restrict__ xin,
                                                     const float* __restrict__ wq,
                                                     const float* __restrict__ wk,
                                                     float* __restrict__ qn,
                                                     float* __restrict__ kn) {
    int which = blockIdx.y;
    const float* wconv = which ? wk : wq;
    float* xout = which ? kn : qn;
    int off = which ? HID_ : 0;
    int bt = blockIdx.x;
    int b = bt >> 10;
    int t = bt & (TT - 1);
    int c = threadIdx.x;
    float4 w4 = *(const float4*)&wconv[c * 4];
    const float* xp = xin + (size_t)b * TT * QS + off + c;
    float acc = 0.f;
    if (t >= 3) acc += xp[(size_t)(t - 3) * QS] * w4.x;
    if (t >= 2) acc += xp[(size_t)(t - 2) * QS] * w4.y;
    if (t >= 1) acc += xp[(size_t)(t - 1) * QS] * w4.z;
    acc += xp[(size_t)t * QS] * w4.w;
    float y = acc / (1.f + expf(-acc));
    __shared__ float wsum[32];
    float ss = y * y;
#pragma unroll
    for (int o = 16; o > 0; o >>= 1) ss += __shfl_xor_sync(0xffffffffu, ss, o);
    if ((c & 31) == 0) wsum[c >> 5] = ss;
    __syncthreads();
    float tot = wsum[(c >> 6) * 2] + wsum[(c >> 6) * 2 + 1];
    xout[(size_t)bt * HID_ + c] = y * rsqrtf(tot + 1e-6f);
}

// ================= pass1: per-chunk(64) local state sums =================
__global__ __launch_bounds__(256) void pass1_kernel(const float* __restrict__ kn,
                                                    const float* __restrict__ qkv,
                                                    const float* __restrict__ gg,
                                                    const float* __restrict__ bet) {
    __shared__ __align__(16) float kc[CHUNK * 64];
    __shared__ __align__(16) float vc[CHUNK * 64];
    __shared__ float ds[CHUNK], ws[CHUNK], gs[CHUNK];
    int blk = blockIdx.x;
    int bh = blk >> 4, c = blk & 15;
    int b = bh >> 4, h = bh & (NH - 1);
    int tid = threadIdx.x;
    int j = tid & 63, rg = tid >> 6;
    size_t rowbase = (size_t)b * TT + c * CHUNK;
    for (int l4 = tid; l4 < CHUNK * 16; l4 += 256) {
        int t = l4 >> 4, d4 = (l4 & 15) << 2;
        *(float4*)&kc[t * 64 + d4] = *(const float4*)&kn[(rowbase + t) * HID_ + h * DH + d4];
        *(float4*)&vc[t * 64 + d4] = *(const float4*)&qkv[(rowbase + t) * QS + 2048 + h * DH + d4];
    }
    if (tid < CHUNK) {
        float g = gg[(rowbase + tid) * NH + h];
        gs[tid] = g;
        ds[tid] = expf(g);
        ws[tid] = bet[(rowbase + tid) * NH + h];
    }
    __syncthreads();
    if (tid == 0) {
        float s = 0.f;
        for (int t = 0; t < CHUNK; t++) s += gs[t];
        g_Dsum[blk] = s;
    }
    float hkk[16], hkv[16];
#pragma unroll
    for (int ii = 0; ii < 16; ii++) { hkk[ii] = 0.f; hkv[ii] = 0.f; }
    for (int t = 0; t < CHUNK; t++) {
        float d = ds[t], w = ws[t];
        float a = w * kc[t * 64 + j];
        float bf = w * vc[t * 64 + j];
        const float4* k4 = (const float4*)&kc[t * 64 + rg * 16];
#pragma unroll
        for (int q = 0; q < 4; q++) {
            float4 kv = k4[q];
            hkk[4*q+0] = d * hkk[4*q+0] + a * kv.x;
            hkk[4*q+1] = d * hkk[4*q+1] + a * kv.y;
            hkk[4*q+2] = d * hkk[4*q+2] + a * kv.z;
            hkk[4*q+3] = d * hkk[4*q+3] + a * kv.w;
            hkv[4*q+0] = d * hkv[4*q+0] + bf * kv.x;
            hkv[4*q+1] = d * hkv[4*q+1] + bf * kv.y;
            hkv[4*q+2] = d * hkv[4*q+2] + bf * kv.z;
            hkv[4*q+3] = d * hkv[4*q+3] + bf * kv.w;
        }
    }
    size_t base = (size_t)blk * 4096;
#pragma unroll
    for (int ii = 0; ii < 16; ii++) {
        g_locKK[base + (rg * 16 + ii) * 64 + j] = hkk[ii];
        g_locKV[base + (rg * 16 + ii) * 64 + j] = hkv[ii];
    }
}

// ================= pass2: per-element chunk-carry scan (even-chunk stores only) =================
__global__ __launch_bounds__(256) void pass2b_kernel() {
    int bh = blockIdx.x >> 4;
    int idx = (blockIdx.x & 15) * 256 + threadIdx.x;
    float cK = 0.f, cV = 0.f;
#pragma unroll
    for (int c = 0; c < NCH; c++) {
        size_t base = ((size_t)bh * NCH + c) * 4096 + idx;
        if ((c & 1) == 0) {
            g_carKK[base] = cK;
            g_carKV[base] = cV;
        }
        float D = expf(g_Dsum[bh * NCH + c]);
        cK = D * cK + g_locKK[base];
        cV = D * cV + g_locKV[base];
    }
}

// ================= fused2: parity-split dual-pipeline CG over 128-step chunks (R10) =================
__global__ __launch_bounds__(256, 2) void fused2_kernel(const float* __restrict__ kn,
                                                        const float* __restrict__ qn,
                                                        const float* __restrict__ qkv,
                                                        const float* __restrict__ gg,
                                                        const float* __restrict__ bet,
                                                        const float* __restrict__ lambda_p,
                                                        const float* __restrict__ norm_w,
                                                        __nv_bfloat16* __restrict__ onA2) {
    __shared__ __align__(16) float kc[CH2 * 64];
    __shared__ float ds[CH2], ws[CH2];
    __shared__ float lams[64], nws[64];
    __shared__ __align__(16) float rsh[2][64];
    __shared__ float red[2][128];
    __shared__ float wu[2][4], wv[2][4];

    int blk = blockIdx.x;
    int bh = blk >> 3, c = blk & 7;
    int b = bh >> 4, h = bh & (NH - 1);
    int tid = threadIdx.x;
    int g = tid >> 7;
    int tg = tid & 127;
    int j = tg & 63, rg = tg >> 6;
    int wig = tg >> 5;
    size_t rowbase = (size_t)b * TT + c * CH2;

    for (int l4 = tid; l4 < CH2 * 16; l4 += 256) {
        int t = l4 >> 4, d4 = (l4 & 15) << 2;
        *(float4*)&kc[t * 64 + d4] = *(const float4*)&kn[(rowbase + t) * HID_ + h * DH + d4];
    }
    if (tid < CH2) {
        ds[tid] = expf(gg[(rowbase + tid) * NH + h]);
        ws[tid] = bet[(rowbase + tid) * NH + h];
    }
    if (tid >= 128 && tid < 192) {
        int jj = tid - 128;
        float lp = lambda_p[h * DH + jj];
        lams[jj] = ((lp > 20.f) ? lp : log1pf(expf(lp))) + 0.25f;
        nws[jj] = norm_w[jj];
    }
    float hkk[32], hkv[32];
    {
        const float* cK = g_carKK + ((size_t)bh * NCH + 2 * c) * 4096;
        const float* cV = g_carKV + ((size_t)bh * NCH + 2 * c) * 4096;
#pragma unroll
        for (int ii = 0; ii < 32; ii++) {
            hkk[ii] = cK[(rg * 32 + ii) * 64 + j];
            hkv[ii] = cV[(rg * 32 + ii) * 64 + j];
        }
    }
    __syncthreads();
    float lam = lams[j];
    float nw = nws[j];

    const float* vbase = qkv + 2048 + h * DH + j;
    const float* qbase = qn + h * DH + j;

    float pv0 = (g == 1) ? vbase[(rowbase + 0) * QS] : 0.f;
    float pv1 = vbase[(rowbase + g) * QS];
    float pq  = qbase[(rowbase + g) * HID_];

    for (int s = 0; s < CH2 / 2; s++) {
        int tt = 2 * s + g;
        float v0 = pv0, v1 = pv1, rhs = pq;
        if (s + 1 < CH2 / 2) {
            int tn = tt + 2;
            pv0 = vbase[(rowbase + tn - 1) * QS];
            pv1 = vbase[(rowbase + tn) * QS];
            pq  = qbase[(rowbase + tn) * HID_];
        }
        if (s > 0 || g == 1) {
            int t = tt - 1;
            float d = ds[t], w = ws[t];
            float a = w * kc[t * 64 + j];
            float bf = w * v0;
            const float4* k4 = (const float4*)&kc[t * 64 + rg * 32];
#pragma unroll
            for (int q = 0; q < 8; q++) {
                float4 kv = k4[q];
                hkk[4*q+0] = d * hkk[4*q+0] + a * kv.x;
                hkk[4*q+1] = d * hkk[4*q+1] + a * kv.y;
                hkk[4*q+2] = d * hkk[4*q+2] + a * kv.z;
                hkk[4*q+3] = d * hkk[4*q+3] + a * kv.w;
                hkv[4*q+0] = d * hkv[4*q+0] + bf * kv.x;
                hkv[4*q+1] = d * hkv[4*q+1] + bf * kv.y;
                hkv[4*q+2] = d * hkv[4*q+2] + bf * kv.z;
                hkv[4*q+3] = d * hkv[4*q+3] + bf * kv.w;
            }
        }
        {
            int t = tt;
            float d = ds[t], w = ws[t];
            float a = w * kc[t * 64 + j];
            float bf = w * v1;
            const float4* k4 = (const float4*)&kc[t * 64 + rg * 32];
#pragma unroll
            for (int q = 0; q < 8; q++) {
                float4 kv = k4[q];
                hkk[4*q+0] = d * hkk[4*q+0] + a * kv.x;
                hkk[4*q+1] = d * hkk[4*q+1] + a * kv.y;
                hkk[4*q+2] = d * hkk[4*q+2] + a * kv.z;
                hkk[4*q+3] = d * hkk[4*q+3] + a * kv.w;
                hkv[4*q+0] = d * hkv[4*q+0] + bf * kv.x;
                hkv[4*q+1] = d * hkv[4*q+1] + bf * kv.y;
                hkv[4*q+2] = d * hkv[4*q+2] + bf * kv.z;
                hkv[4*q+3] = d * hkv[4*q+3] + bf * kv.w;
            }
        }
        float r = rhs;
        float x = 0.f, p = 0.f, sv = 0.f;
        float mu_prev = 1.f, alpha_prev = 1.f;
        if (rg == 0) rsh[g][j] = r;
        for (int it = 0; it < NCG; it++) {
            __syncthreads();
            const float4* r4 = (const float4*)&rsh[g][rg * 32];
            float spart = 0.f;
#pragma unroll
            for (int q = 0; q < 8; q++) {
                float4 rv = r4[q];
                spart += hkk[4*q+0]*rv.x + hkk[4*q+1]*rv.y + hkk[4*q+2]*rv.z + hkk[4*q+3]*rv.w;
            }
            red[g][rg * 64 + j] = spart;
            float rr = r * r;
            float u = 0.5f * rr;
            float v = r * spart + 0.5f * lam * rr;
#pragma unroll
            for (int o = 16; o > 0; o >>= 1) {
                u += __shfl_xor_sync(0xffffffffu, u, o);
                v += __shfl_xor_sync(0xffffffffu, v, o);
            }
            if ((tg & 31) == 0) { wu[g][wig] = u; wv[g][wig] = v; }
            __syncthreads();
            float mu = (wu[g][0] + wu[g][1]) + (wu[g][2] + wu[g][3]);
            float dl = (wv[g][0] + wv[g][1]) + (wv[g][2] + wv[g][3]);
            float Ap = lam * r + red[g][j] + red[g][64 + j];
            float beta = (it == 0) ? 0.f : mu / (mu_prev + 1e-12f);
            float alpha = mu / ((dl - beta * mu / alpha_prev) + 1e-12f);
            p = r + beta * p;
            sv = Ap + beta * sv;
            x += alpha * p;
            mu_prev = mu; alpha_prev = alpha;
            if (it < NCG - 1) {
                r -= alpha * sv;
                if (rg == 0) rsh[g][j] = r;
            }
        }
        __syncthreads();
        if (rg == 0) rsh[g][j] = x;
        __syncthreads();
        {
            const float4* x4 = (const float4*)&rsh[g][rg * 32];
            float opart = 0.f;
#pragma unroll
            for (int q = 0; q < 8; q++) {
                float4 xv = x4[q];
                opart += hkv[4*q+0]*xv.x + hkv[4*q+1]*xv.y + hkv[4*q+2]*xv.z + hkv[4*q+3]*xv.w;
            }
            red[g][rg * 64 + j] = opart;
        }
        __syncthreads();
        float o = red[g][j] + red[g][64 + j];
        float u2 = 0.5f * o * o;
#pragma unroll
        for (int oo = 16; oo > 0; oo >>= 1) u2 += __shfl_xor_sync(0xffffffffu, u2, oo);
        if ((tg & 31) == 0) wu[g][wig] = u2;
        __syncthreads();
        float ssum = (wu[g][0] + wu[g][1]) + (wu[g][2] + wu[g][3]);
        if (rg == 0) {
            float on = o * rsqrtf(ssum * (1.f / 64.f) + 1e-5f) * nw;
            __nv_bfloat16 hi = __float2bfloat16(on);
            __nv_bfloat16 lo = __float2bfloat16(on - __bfloat162float(hi));
            size_t base2 = (rowbase + tt) * KP + h * DH + j;
            onA2[base2] = hi;
            onA2[base2 + HID_] = lo;
            onA2[base2 + 2 * HID_] = hi;
        }
        __syncthreads();
    }
}

// ================= host launcher =================
extern "C" void kernel_launch(void* const* d_in, const int* in_sizes, int n_in,
                              void* d_out, int out_size) {
    const float* X        = (const float*)d_in[0];
    const float* Wq       = (const float*)d_in[1];
    const float* Wk       = (const float*)d_in[2];
    const float* Wv       = (const float*)d_in[3];
    const float* Wa       = (const float*)d_in[4];
    const float* Wb       = (const float*)d_in[5];
    const float* bb       = (const float*)d_in[6];
    const float* A_log    = (const float*)d_in[7];
    const float* dt_bias  = (const float*)d_in[8];
    const float* lambda_p = (const float*)d_in[9];
    const float* Wconv_q  = (const float*)d_in[10];
    const float* Wconv_k  = (const float*)d_in[11];
    const float* norm_w   = (const float*)d_in[12];
    const float* Wo       = (const float*)d_in[13];

    float *qkv, *qn, *kn, *beta, *gdec;
    __nv_bfloat16 *XA2, *W2q, *W2o, *onA2;
    cudaGetSymbolAddress((void**)&qkv,  g_qkv);
    cudaGetSymbolAddress((void**)&qn,   g_qn);
    cudaGetSymbolAddress((void**)&kn,   g_kn);
    cudaGetSymbolAddress((void**)&beta, g_beta);
    cudaGetSymbolAddress((void**)&gdec, g_gg);
    cudaGetSymbolAddress((void**)&XA2,  g_XA2);
    cudaGetSymbolAddress((void**)&W2q,  g_W2q);
    cudaGetSymbolAddress((void**)&W2o,  g_W2o);
    cudaGetSymbolAddress((void**)&onA2, g_onA2);

    const int MMA_SMEM = NSTG * 20480;   // 81920
    cudaFuncSetAttribute(mma_gemm, cudaFuncAttributeMaxDynamicSharedMemorySize, MMA_SMEM);

    const int M = BB * TT;

    splitX<<<(M * HID_) / 256, 256>>>(X, XA2);                             // 1
    transW<<<dim3(96, 32), 256>>>(Wq, Wk, Wv, W2q);                        // 2
    transAB<<<8, 256>>>(Wa, Wb, W2q);                                      // 3
    mma_gemm<<<dim3(NQ / 128, 16), 256, MMA_SMEM>>>(XA2, W2q, qkv, NQ);    // 4 <- profiled
    transW<<<dim3(32, 32), 256>>>(Wo, Wo, Wo, W2o);                        // 5
    abpost<<<(M * NH) / 256, 256>>>(qkv, bb, A_log, dt_bias, beta, gdec);
    conv2_kernel<<<dim3(M, 2), 1024>>>(qkv, Wconv_q, Wconv_k, qn, kn);
    pass1_kernel<<<BB * NH * NCH, 256>>>(kn, qkv, gdec, beta);
    pass2b_kernel<<<BB * NH * 16, 256>>>();
    fused2_kernel<<<BB * NH * NCH2, 256>>>(kn, qn, qkv, gdec, beta, lambda_p, norm_w, onA2);
    mma_gemm<<<dim3(8, 16), 256, MMA_SMEM>>>(onA2, W2o, (float*)d_out, HID_);
}

// round 14
// speedup vs baseline: 1.6745x; 1.0003x over previous
#include <cuda_runtime.h>
#include <cuda_bf16.h>
#include <cstdint>

#define BB    2
#define TT    1024
#define HID_  1024
#define NH    16
#define DH    64
#define NCG   15
#define CHUNK 64
#define NCH   (TT/CHUNK)   // 16
#define CH2   64           // fused2 chunk (was 128)
#define NCH2  (TT/CH2)     // 16
#define KP    (3*HID_)
#define NQ    3200
#define QS    3200
#define LDT   40
#define BK    32
#define NSTG  4

// ---------------- device scratch ----------------
__device__ float g_qkv [BB*TT*QS];
__device__ float g_qn  [BB*TT*HID_];
__device__ float g_kn  [BB*TT*HID_];
__device__ float g_beta[BB*TT*NH];
__device__ float g_gg  [BB*TT*NH];
__device__ float g_locKK[BB*NH*NCH*DH*DH];
__device__ float g_locKV[BB*NH*NCH*DH*DH];
__device__ float g_carKK[BB*NH*NCH*DH*DH];
__device__ float g_carKV[BB*NH*NCH*DH*DH];
__device__ float g_Dsum [BB*NH*NCH];
__device__ __nv_bfloat16 g_XA2 [BB*TT*KP];
__device__ __nv_bfloat16 g_W2q [NQ*KP];
__device__ __nv_bfloat16 g_W2o [HID_*KP];
__device__ __nv_bfloat16 g_onA2[BB*TT*KP];

// ================= helpers =================
__device__ __forceinline__ uint32_t smem_u32(const void* p) {
    uint32_t a;
    asm("{ .reg .u64 t; cvta.to.shared.u64 t, %1; cvt.u32.u64 %0, t; }" : "=r"(a) : "l"(p));
    return a;
}
__device__ __forceinline__ void cpasync16(uint32_t dst, const void* src) {
    asm volatile("cp.async.ca.shared.global [%0], [%1], 16;" :: "r"(dst), "l"(src));
}
__device__ __forceinline__ void ldsm4(uint32_t& r0, uint32_t& r1, uint32_t& r2, uint32_t& r3, uint32_t addr) {
    asm volatile("ldmatrix.sync.aligned.m8n8.x4.shared.b16 {%0,%1,%2,%3}, [%4];"
                 : "=r"(r0), "=r"(r1), "=r"(r2), "=r"(r3) : "r"(addr));
}
__device__ __forceinline__ void mma16816(float* c, uint32_t a0, uint32_t a1, uint32_t a2, uint32_t a3,
                                         uint32_t b0, uint32_t b1) {
    asm volatile("mma.sync.aligned.m16n8k16.row.col.f32.bf16.bf16.f32 "
                 "{%0,%1,%2,%3}, {%4,%5,%6,%7}, {%8,%9}, {%0,%1,%2,%3};"
                 : "+f"(c[0]), "+f"(c[1]), "+f"(c[2]), "+f"(c[3])
                 : "r"(a0), "r"(a1), "r"(a2), "r"(a3), "r"(b0), "r"(b1));
}

// ================= HMMA GEMM: 128x128 tile, 8 warps 64x32, 4-stage cp.async (R10 config) =================
__global__ __launch_bounds__(256, 2) void mma_gemm(const __nv_bfloat16* __restrict__ A,
                                                   const __nv_bfloat16* __restrict__ B,
                                                   float* __restrict__ C, int N) {
    extern __shared__ __align__(16) char dsm[];
    uint32_t smbase = smem_u32(dsm);
    int tid = threadIdx.x, lane = tid & 31, wid = tid >> 5;
    int wrow = wid >> 2, wcol = wid & 3;
    int bm = blockIdx.y * 128, bn = blockIdx.x * 128;
    const __nv_bfloat16* Ap = A + (size_t)bm * KP;
    const __nv_bfloat16* Bp = B + (size_t)bn * KP;

    float acc[16][4];
#pragma unroll
    for (int i = 0; i < 16; i++)
#pragma unroll
        for (int j = 0; j < 4; j++) acc[i][j] = 0.f;

    int li0r = tid >> 2, li0c = (tid & 3) << 3;
    int li1r = (tid + 256) >> 2, li1c = li0c;

    auto issue = [&](int s) {
        int buf = s & (NSTG - 1);
        int kb = s * BK;
        uint32_t ab = smbase + buf * 20480;
        cpasync16(ab + li0r * 80 + li0c * 2, Ap + (size_t)li0r * KP + kb + li0c);
        cpasync16(ab + li1r * 80 + li1c * 2, Ap + (size_t)li1r * KP + kb + li1c);
        uint32_t bb2 = ab + 10240;
        cpasync16(bb2 + li0r * 80 + li0c * 2, Bp + (size_t)li0r * KP + kb + li0c);
        cpasync16(bb2 + li1r * 80 + li1c * 2, Bp + (size_t)li1r * KP + kb + li1c);
        asm volatile("cp.async.commit_group;");
    };

    const int nk = KP / BK;  // 96
    issue(0); issue(1); issue(2);

    int bgrp = lane >> 3, brow = lane & 7;
    int bn_off = ((bgrp & 2) ? 8 : 0) + brow;
    int bk_off = (bgrp & 1) ? 8 : 0;

    for (int k = 0; k < nk; k++) {
        if (k + 3 < nk) asm volatile("cp.async.wait_group 2;");
        else            asm volatile("cp.async.wait_group 0;");
        __syncthreads();
        if (k + 3 < nk) issue(k + 3);

        int buf = k & (NSTG - 1);
        uint32_t abase = smbase + buf * 20480;
        uint32_t bbase = abase + 10240;
#pragma unroll
        for (int ks = 0; ks < 2; ks++) {
            uint32_t a[4][4];
#pragma unroll
            for (int mt = 0; mt < 4; mt++) {
                int row = wrow * 64 + mt * 16 + (lane & 15);
                int col = ks * 16 + (lane >> 4) * 8;
                ldsm4(a[mt][0], a[mt][1], a[mt][2], a[mt][3], abase + (row * LDT + col) * 2);
            }
            uint32_t bf[2][4];
#pragma unroll
            for (int ntp = 0; ntp < 2; ntp++) {
                int n = wcol * 32 + ntp * 16 + bn_off;
                int kk = ks * 16 + bk_off;
                ldsm4(bf[ntp][0], bf[ntp][1], bf[ntp][2], bf[ntp][3], bbase + (n * LDT + kk) * 2);
            }
#pragma unroll
            for (int mt = 0; mt < 4; mt++)
#pragma unroll
                for (int ntp = 0; ntp < 2; ntp++) {
                    mma16816(acc[mt * 4 + 2 * ntp],
                             a[mt][0], a[mt][1], a[mt][2], a[mt][3], bf[ntp][0], bf[ntp][1]);
                    mma16816(acc[mt * 4 + 2 * ntp + 1],
                             a[mt][0], a[mt][1], a[mt][2], a[mt][3], bf[ntp][2], bf[ntp][3]);
                }
        }
    }

#pragma unroll
    for (int mt = 0; mt < 4; mt++) {
#pragma unroll
        for (int nt = 0; nt < 4; nt++) {
            float* c = acc[mt * 4 + nt];
            int row = bm + wrow * 64 + mt * 16 + (lane >> 2);
            int col = bn + wcol * 32 + nt * 8 + (lane & 3) * 2;
            *(float2*)&C[(size_t)row * N + col] = make_float2(c[0], c[1]);
            *(float2*)&C[(size_t)(row + 8) * N + col] = make_float2(c[2], c[3]);
        }
    }
}

// ================= HMMA GEMM 64x128 tile (for low-block-count GEMM2): 8 warps 32x32 =================
// smem/stage: A 64*80=5120 + B 128*80=10240 = 15360; 4 stages = 61440 B
__global__ __launch_bounds__(256, 2) void mma_gemm64(const __nv_bfloat16* __restrict__ A,
                                                     const __nv_bfloat16* __restrict__ B,
                                                     float* __restrict__ C, int N) {
    extern __shared__ __align__(16) char dsm[];
    uint32_t smbase = smem_u32(dsm);
    int tid = threadIdx.x, lane = tid & 31, wid = tid >> 5;
    int wrow = wid >> 2, wcol = wid & 3;        // 2 x 4 warp grid, warp tile 32x32
    int bm = blockIdx.y * 64, bn = blockIdx.x * 128;
    const __nv_bfloat16* Ap = A + (size_t)bm * KP;
    const __nv_bfloat16* Bp = B + (size_t)bn * KP;

    float acc[8][4];
#pragma unroll
    for (int i = 0; i < 8; i++)
#pragma unroll
        for (int j = 0; j < 4; j++) acc[i][j] = 0.f;

    int lar = tid >> 2, lac = (tid & 3) << 3;           // A: 256 chunks, 1/thread
    int lb0r = tid >> 2, lb0c = lac;                    // B: 512 chunks, 2/thread
    int lb1r = (tid + 256) >> 2, lb1c = lac;

    auto issue = [&](int s) {
        int buf = s & (NSTG - 1);
        int kb = s * BK;
        uint32_t ab = smbase + buf * 15360;
        cpasync16(ab + lar * 80 + lac * 2, Ap + (size_t)lar * KP + kb + lac);
        uint32_t bb2 = ab + 5120;
        cpasync16(bb2 + lb0r * 80 + lb0c * 2, Bp + (size_t)lb0r * KP + kb + lb0c);
        cpasync16(bb2 + lb1r * 80 + lb1c * 2, Bp + (size_t)lb1r * KP + kb + lb1c);
        asm volatile("cp.async.commit_group;");
    };

    const int nk = KP / BK;  // 96
    issue(0); issue(1); issue(2);

    int bgrp = lane >> 3, brow = lane & 7;
    int bn_off = ((bgrp & 2) ? 8 : 0) + brow;
    int bk_off = (bgrp & 1) ? 8 : 0;

    for (int k = 0; k < nk; k++) {
        if (k + 3 < nk) asm volatile("cp.async.wait_group 2;");
        else            asm volatile("cp.async.wait_group 0;");
        __syncthreads();
        if (k + 3 < nk) issue(k + 3);

        int buf = k & (NSTG - 1);
        uint32_t abase = smbase + buf * 15360;
        uint32_t bbase = abase + 5120;
#pragma unroll
        for (int ks = 0; ks < 2; ks++) {
            uint32_t a[2][4];
#pragma unroll
            for (int mt = 0; mt < 2; mt++) {
                int row = wrow * 32 + mt * 16 + (lane & 15);
                int col = ks * 16 + (lane >> 4) * 8;
                ldsm4(a[mt][0], a[mt][1], a[mt][2], a[mt][3], abase + (row * LDT + col) * 2);
            }
            uint32_t bf[2][4];
#pragma unroll
            for (int ntp = 0; ntp < 2; ntp++) {
                int n = wcol * 32 + ntp * 16 + bn_off;
                int kk = ks * 16 + bk_off;
                ldsm4(bf[ntp][0], bf[ntp][1], bf[ntp][2], bf[ntp][3], bbase + (n * LDT + kk) * 2);
            }
#pragma unroll
            for (int mt = 0; mt < 2; mt++)
#pragma unroll
                for (int ntp = 0; ntp < 2; ntp++) {
                    mma16816(acc[mt * 4 + 2 * ntp],
                             a[mt][0], a[mt][1], a[mt][2], a[mt][3], bf[ntp][0], bf[ntp][1]);
                    mma16816(acc[mt * 4 + 2 * ntp + 1],
                             a[mt][0], a[mt][1], a[mt][2], a[mt][3], bf[ntp][2], bf[ntp][3]);
                }
        }
    }

#pragma unroll
    for (int mt = 0; mt < 2; mt++) {
#pragma unroll
        for (int nt = 0; nt < 4; nt++) {
            float* c = acc[mt * 4 + nt];
            int row = bm + wrow * 32 + mt * 16 + (lane >> 2);
            int col = bn + wcol * 32 + nt * 8 + (lane & 3) * 2;
            *(float2*)&C[(size_t)row * N + col] = make_float2(c[0], c[1]);
            *(float2*)&C[(size_t)(row + 8) * N + col] = make_float2(c[2], c[3]);
        }
    }
}

// ================= split X into [hi | lo | hi] =================
__global__ __launch_bounds__(256) void splitX(const float* __restrict__ X,
                                              __nv_bfloat16* __restrict__ A2) {
    int i = blockIdx.x * 256 + threadIdx.x;
    int row = i >> 10, k = i & 1023;
    float v = X[i];
    __nv_bfloat16 h = __float2bfloat16(v);
    __nv_bfloat16 l = __float2bfloat16(v - __bfloat162float(h));
    size_t base = (size_t)row * KP;
    A2[base + k] = h;
    A2[base + HID_ + k] = l;
    A2[base + 2 * HID_ + k] = h;
}

// ================= transpose + split weights =================
__global__ __launch_bounds__(256) void transW(const float* __restrict__ W0,
                                              const float* __restrict__ W1,
                                              const float* __restrict__ W2,
                                              __nv_bfloat16* __restrict__ B2) {
    __shared__ float ts[32][33];
    int nt = blockIdx.x, kt = blockIdx.y;
    int tx = threadIdx.x & 31, ty = threadIdx.x >> 5;
    int n0 = nt * 32, k0 = kt * 32;
    const float* W = (n0 < 1024) ? W0 : ((n0 < 2048) ? W1 : W2);
    int nc = n0 & 1023;
#pragma unroll
    for (int i = 0; i < 32; i += 8)
        ts[ty + i][tx] = W[(size_t)(k0 + ty + i) * 1024 + nc + tx];
    __syncthreads();
#pragma unroll
    for (int i = 0; i < 32; i += 8) {
        int n = n0 + ty + i, k = k0 + tx;
        float v = ts[tx][ty + i];
        __nv_bfloat16 h = __float2bfloat16(v);
        __nv_bfloat16 l = __float2bfloat16(v - __bfloat162float(h));
        size_t base = (size_t)n * KP;
        B2[base + k] = h;
        B2[base + HID_ + k] = h;
        B2[base + 2 * HID_ + k] = l;
    }
}

// ================= Wa/Wb into GEMM rows 3072..3103 =================
__global__ __launch_bounds__(256) void transAB(const float* __restrict__ Wa,
                                               const float* __restrict__ Wb,
                                               __nv_bfloat16* __restrict__ B2) {
    int n = blockIdx.x * 4 + (threadIdx.x >> 6);
    int t64 = threadIdx.x & 63;
    const float* W = (n < 16) ? Wa : Wb;
    int h = n & 15;
    size_t base = (size_t)(3072 + n) * KP;
    for (int k = t64; k < HID_; k += 64) {
        float v = W[(size_t)k * NH + h];
        __nv_bfloat16 hh = __float2bfloat16(v);
        __nv_bfloat16 ll = __float2bfloat16(v - __bfloat162float(hh));
        B2[base + k] = hh;
        B2[base + HID_ + k] = hh;
        B2[base + 2 * HID_ + k] = ll;
    }
}

// ================= beta/g epilogue =================
__global__ __launch_bounds__(256) void abpost(const float* __restrict__ C,
                                              const float* __restrict__ bb,
                                              const float* __restrict__ A_log,
                                              const float* __restrict__ dt_bias,
                                              float* __restrict__ beta_o,
                                              float* __restrict__ g_o) {
    int i = blockIdx.x * 256 + threadIdx.x;
    int row = i >> 4, h = i & 15;
    float sa = C[(size_t)row * QS + 3072 + h];
    float sb = C[(size_t)row * QS + 3088 + h];
    float bv = 1.f / (1.f + expf(-(sb + bb[h])));
    float av = sa + dt_bias[h];
    float sp = (av > 20.f) ? av : log1pf(expf(av));
    beta_o[(size_t)row * NH + h] = bv;
    g_o[(size_t)row * NH + h] = -expf(A_log[h]) * sp;
}

// ================= merged conv + silu + per-head l2norm =================
__global__ __launch_bounds__(1024) void conv2_kernel(const float* __restrict__ xin,
                                                     const float* __restrict__ wq,
                                                     const float* __restrict__ wk,
                                                     float* __restrict__ qn,
                                                     float* __restrict__ kn) {
    int which = blockIdx.y;
    const float* wconv = which ? wk : wq;
    float* xout = which ? kn : qn;
    int off = which ? HID_ : 0;
    int bt = blockIdx.x;
    int b = bt >> 10;
    int t = bt & (TT - 1);
    int c = threadIdx.x;
    float4 w4 = *(const float4*)&wconv[c * 4];
    const float* xp = xin + (size_t)b * TT * QS + off + c;
    float acc = 0.f;
    if (t >= 3) acc += xp[(size_t)(t - 3) * QS] * w4.x;
    if (t >= 2) acc += xp[(size_t)(t - 2) * QS] * w4.y;
    if (t >= 1) acc += xp[(size_t)(t - 1) * QS] * w4.z;
    acc += xp[(size_t)t * QS] * w4.w;
    float y = acc / (1.f + expf(-acc));
    __shared__ float wsum[32];
    float ss = y * y;
#pragma unroll
    for (int o = 16; o > 0; o >>= 1) ss += __shfl_xor_sync(0xffffffffu, ss, o);
    if ((c & 31) == 0) wsum[c >> 5] = ss;
    __syncthreads();
    float tot = wsum[(c >> 6) * 2] + wsum[(c >> 6) * 2 + 1];
    xout[(size_t)bt * HID_ + c] = y * rsqrtf(tot + 1e-6f);
}

// ================= pass1: per-chunk(64) local state sums =================
__global__ __launch_bounds__(256) void pass1_kernel(const float* __restrict__ kn,
                                                    const float* __restrict__ qkv,
                                                    const float* __restrict__ gg,
                                                    const float* __restrict__ bet) {
    __shared__ __align__(16) float kc[CHUNK * 64];
    __shared__ __align__(16) float vc[CHUNK * 64];
    __shared__ float ds[CHUNK], ws[CHUNK], gs[CHUNK];
    int blk = blockIdx.x;
    int bh = blk >> 4, c = blk & 15;
    int b = bh >> 4, h = bh & (NH - 1);
    int tid = threadIdx.x;
    int j = tid & 63, rg = tid >> 6;
    size_t rowbase = (size_t)b * TT + c * CHUNK;
    for (int l4 = tid; l4 < CHUNK * 16; l4 += 256) {
        int t = l4 >> 4, d4 = (l4 & 15) << 2;
        *(float4*)&kc[t * 64 + d4] = *(const float4*)&kn[(rowbase + t) * HID_ + h * DH + d4];
        *(float4*)&vc[t * 64 + d4] = *(const float4*)&qkv[(rowbase + t) * QS + 2048 + h * DH + d4];
    }
    if (tid < CHUNK) {
        float g = gg[(rowbase + tid) * NH + h];
        gs[tid] = g;
        ds[tid] = expf(g);
        ws[tid] = bet[(rowbase + tid) * NH + h];
    }
    __syncthreads();
    if (tid == 0) {
        float s = 0.f;
        for (int t = 0; t < CHUNK; t++) s += gs[t];
        g_Dsum[blk] = s;
    }
    float hkk[16], hkv[16];
#pragma unroll
    for (int ii = 0; ii < 16; ii++) { hkk[ii] = 0.f; hkv[ii] = 0.f; }
    for (int t = 0; t < CHUNK; t++) {
        float d = ds[t], w = ws[t];
        float a = w * kc[t * 64 + j];
        float bf = w * vc[t * 64 + j];
        const float4* k4 = (const float4*)&kc[t * 64 + rg * 16];
#pragma unroll
        for (int q = 0; q < 4; q++) {
            float4 kv = k4[q];
            hkk[4*q+0] = d * hkk[4*q+0] + a * kv.x;
            hkk[4*q+1] = d * hkk[4*q+1] + a * kv.y;
            hkk[4*q+2] = d * hkk[4*q+2] + a * kv.z;
            hkk[4*q+3] = d * hkk[4*q+3] + a * kv.w;
            hkv[4*q+0] = d * hkv[4*q+0] + bf * kv.x;
            hkv[4*q+1] = d * hkv[4*q+1] + bf * kv.y;
            hkv[4*q+2] = d * hkv[4*q+2] + bf * kv.z;
            hkv[4*q+3] = d * hkv[4*q+3] + bf * kv.w;
        }
    }
    size_t base = (size_t)blk * 4096;
#pragma unroll
    for (int ii = 0; ii < 16; ii++) {
        g_locKK[base + (rg * 16 + ii) * 64 + j] = hkk[ii];
        g_locKV[base + (rg * 16 + ii) * 64 + j] = hkv[ii];
    }
}

// ================= pass2: per-element chunk-carry scan (all chunks) =================
__global__ __launch_bounds__(256) void pass2b_kernel() {
    int bh = blockIdx.x >> 4;
    int idx = (blockIdx.x & 15) * 256 + threadIdx.x;
    float cK = 0.f, cV = 0.f;
#pragma unroll
    for (int c = 0; c < NCH; c++) {
        size_t base = ((size_t)bh * NCH + c) * 4096 + idx;
        g_carKK[base] = cK;
        g_carKV[base] = cV;
        float D = expf(g_Dsum[bh * NCH + c]);
        cK = D * cK + g_locKK[base];
        cV = D * cV + g_locKV[base];
    }
}

// ================= fused2: parity-split dual-pipeline CG over 64-step chunks =================
__global__ __launch_bounds__(256, 2) void fused2_kernel(const float* __restrict__ kn,
                                                        const float* __restrict__ qn,
                                                        const float* __restrict__ qkv,
                                                        const float* __restrict__ gg,
                                                        const float* __restrict__ bet,
                                                        const float* __restrict__ lambda_p,
                                                        const float* __restrict__ norm_w,
                                                        __nv_bfloat16* __restrict__ onA2) {
    __shared__ __align__(16) float kc[CH2 * 64];
    __shared__ float ds[CH2], ws[CH2];
    __shared__ float lams[64], nws[64];
    __shared__ __align__(16) float rsh[2][64];
    __shared__ float red[2][128];
    __shared__ float wu[2][4], wv[2][4];

    int blk = blockIdx.x;                    // 512 blocks
    int bh = blk >> 4, c = blk & 15;         // c in [0,16)
    int b = bh >> 4, h = bh & (NH - 1);
    int tid = threadIdx.x;
    int g = tid >> 7;
    int tg = tid & 127;
    int j = tg & 63, rg = tg >> 6;
    int wig = tg >> 5;
    size_t rowbase = (size_t)b * TT + c * CH2;

    for (int l4 = tid; l4 < CH2 * 16; l4 += 256) {
        int t = l4 >> 4, d4 = (l4 & 15) << 2;
        *(float4*)&kc[t * 64 + d4] = *(const float4*)&kn[(rowbase + t) * HID_ + h * DH + d4];
    }
    if (tid < CH2) {
        ds[tid] = expf(gg[(rowbase + tid) * NH + h]);
        ws[tid] = bet[(rowbase + tid) * NH + h];
    }
    if (tid >= 128 && tid < 192) {
        int jj = tid - 128;
        float lp = lambda_p[h * DH + jj];
        lams[jj] = ((lp > 20.f) ? lp : log1pf(expf(lp))) + 0.25f;
        nws[jj] = norm_w[jj];
    }
    float hkk[32], hkv[32];
    {
        const float* cK = g_carKK + ((size_t)bh * NCH + c) * 4096;
        const float* cV = g_carKV + ((size_t)bh * NCH + c) * 4096;
#pragma unroll
        for (int ii = 0; ii < 32; ii++) {
            hkk[ii] = cK[(rg * 32 + ii) * 64 + j];
            hkv[ii] = cV[(rg * 32 + ii) * 64 + j];
        }
    }
    __syncthreads();
    float lam = lams[j];
    float nw = nws[j];

    const float* vbase = qkv + 2048 + h * DH + j;
    const float* qbase = qn + h * DH + j;

    float pv0 = (g == 1) ? vbase[(rowbase + 0) * QS] : 0.f;
    float pv1 = vbase[(rowbase + g) * QS];
    float pq  = qbase[(rowbase + g) * HID_];

    for (int s = 0; s < CH2 / 2; s++) {
        int tt = 2 * s + g;
        float v0 = pv0, v1 = pv1, rhs = pq;
        if (s + 1 < CH2 / 2) {
            int tn = tt + 2;
            pv0 = vbase[(rowbase + tn - 1) * QS];
            pv1 = vbase[(rowbase + tn) * QS];
            pq  = qbase[(rowbase + tn) * HID_];
        }
        if (s > 0 || g == 1) {
            int t = tt - 1;
            float d = ds[t], w = ws[t];
            float a = w * kc[t * 64 + j];
            float bf = w * v0;
            const float4* k4 = (const float4*)&kc[t * 64 + rg * 32];
#pragma unroll
            for (int q = 0; q < 8; q++) {
                float4 kv = k4[q];
                hkk[4*q+0] = d * hkk[4*q+0] + a * kv.x;
                hkk[4*q+1] = d * hkk[4*q+1] + a * kv.y;
                hkk[4*q+2] = d * hkk[4*q+2] + a * kv.z;
                hkk[4*q+3] = d * hkk[4*q+3] + a * kv.w;
                hkv[4*q+0] = d * hkv[4*q+0] + bf * kv.x;
                hkv[4*q+1] = d * hkv[4*q+1] + bf * kv.y;
                hkv[4*q+2] = d * hkv[4*q+2] + bf * kv.z;
                hkv[4*q+3] = d * hkv[4*q+3] + bf * kv.w;
            }
        }
        {
            int t = tt;
            float d = ds[t], w = ws[t];
            float a = w * kc[t * 64 + j];
            float bf = w * v1;
            const float4* k4 = (const float4*)&kc[t * 64 + rg * 32];
#pragma unroll
            for (int q = 0; q < 8; q++) {
                float4 kv = k4[q];
                hkk[4*q+0] = d * hkk[4*q+0] + a * kv.x;
                hkk[4*q+1] = d * hkk[4*q+1] + a * kv.y;
                hkk[4*q+2] = d * hkk[4*q+2] + a * kv.z;
                hkk[4*q+3] = d * hkk[4*q+3] + a * kv.w;
                hkv[4*q+0] = d * hkv[4*q+0] + bf * kv.x;
                hkv[4*q+1] = d * hkv[4*q+1] + bf * kv.y;
                hkv[4*q+2] = d * hkv[4*q+2] + bf * kv.z;
                hkv[4*q+3] = d * hkv[4*q+3] + bf * kv.w;
            }
        }
        float r = rhs;
        float x = 0.f, p = 0.f, sv = 0.f;
        float mu_prev = 1.f, alpha_prev = 1.f;
        if (rg == 0) rsh[g][j] = r;
        for (int it = 0; it < NCG; it++) {
            __syncthreads();
            const float4* r4 = (const float4*)&rsh[g][rg * 32];
            float spart = 0.f;
#pragma unroll
            for (int q = 0; q < 8; q++) {
                float4 rv = r4[q];
                spart += hkk[4*q+0]*rv.x + hkk[4*q+1]*rv.y + hkk[4*q+2]*rv.z + hkk[4*q+3]*rv.w;
            }
            red[g][rg * 64 + j] = spart;
            float rr = r * r;
            float u = 0.5f * rr;
            float v = r * spart + 0.5f * lam * rr;
#pragma unroll
            for (int o = 16; o > 0; o >>= 1) {
                u += __shfl_xor_sync(0xffffffffu, u, o);
                v += __shfl_xor_sync(0xffffffffu, v, o);
            }
            if ((tg & 31) == 0) { wu[g][wig] = u; wv[g][wig] = v; }
            __syncthreads();
            float mu = (wu[g][0] + wu[g][1]) + (wu[g][2] + wu[g][3]);
            float dl = (wv[g][0] + wv[g][1]) + (wv[g][2] + wv[g][3]);
            float Ap = lam * r + red[g][j] + red[g][64 + j];
            float beta = (it == 0) ? 0.f : mu / (mu_prev + 1e-12f);
            float alpha = mu / ((dl - beta * mu / alpha_prev) + 1e-12f);
            p = r + beta * p;
            sv = Ap + beta * sv;
            x += alpha * p;
            mu_prev = mu; alpha_prev = alpha;
            if (it < NCG - 1) {
                r -= alpha * sv;
                if (rg == 0) rsh[g][j] = r;
            }
        }
        __syncthreads();
        if (rg == 0) rsh[g][j] = x;
        __syncthreads();
        {
            const float4* x4 = (const float4*)&rsh[g][rg * 32];
            float opart = 0.f;
#pragma unroll
            for (int q = 0; q < 8; q++) {
                float4 xv = x4[q];
                opart += hkv[4*q+0]*xv.x + hkv[4*q+1]*xv.y + hkv[4*q+2]*xv.z + hkv[4*q+3]*xv.w;
            }
            red[g][rg * 64 + j] = opart;
        }
        __syncthreads();
        float o = red[g][j] + red[g][64 + j];
        float u2 = 0.5f * o * o;
#pragma unroll
        for (int oo = 16; oo > 0; oo >>= 1) u2 += __shfl_xor_sync(0xffffffffu, u2, oo);
        if ((tg & 31) == 0) wu[g][wig] = u2;
        __syncthreads();
        float ssum = (wu[g][0] + wu[g][1]) + (wu[g][2] + wu[g][3]);
        if (rg == 0) {
            float on = o * rsqrtf(ssum * (1.f / 64.f) + 1e-5f) * nw;
            __nv_bfloat16 hi = __float2bfloat16(on);
            __nv_bfloat16 lo = __float2bfloat16(on - __bfloat162float(hi));
            size_t base2 = (rowbase + tt) * KP + h * DH + j;
            onA2[base2] = hi;
            onA2[base2 + HID_] = lo;
            onA2[base2 + 2 * HID_] = hi;
        }
        __syncthreads();
    }
}

// ================= host launcher =================
extern "C" void kernel_launch(void* const* d_in, const int* in_sizes, int n_in,
                              void* d_out, int out_size) {
    const float* X        = (const float*)d_in[0];
    const float* Wq       = (const float*)d_in[1];
    const float* Wk       = (const float*)d_in[2];
    const float* Wv       = (const float*)d_in[3];
    const float* Wa       = (const float*)d_in[4];
    const float* Wb       = (const float*)d_in[5];
    const float* bb       = (const float*)d_in[6];
    const float* A_log    = (const float*)d_in[7];
    const float* dt_bias  = (const float*)d_in[8];
    const float* lambda_p = (const float*)d_in[9];
    const float* Wconv_q  = (const float*)d_in[10];
    const float* Wconv_k  = (const float*)d_in[11];
    const float* norm_w   = (const float*)d_in[12];
    const float* Wo       = (const float*)d_in[13];

    float *qkv, *qn, *kn, *beta, *gdec;
    __nv_bfloat16 *XA2, *W2q, *W2o, *onA2;
    cudaGetSymbolAddress((void**)&qkv,  g_qkv);
    cudaGetSymbolAddress((void**)&qn,   g_qn);
    cudaGetSymbolAddress((void**)&kn,   g_kn);
    cudaGetSymbolAddress((void**)&beta, g_beta);
    cudaGetSymbolAddress((void**)&gdec, g_gg);
    cudaGetSymbolAddress((void**)&XA2,  g_XA2);
    cudaGetSymbolAddress((void**)&W2q,  g_W2q);
    cudaGetSymbolAddress((void**)&W2o,  g_W2o);
    cudaGetSymbolAddress((void**)&onA2, g_onA2);

    const int MMA_SMEM  = NSTG * 20480;   // 81920
    const int MMA_SMEM64 = NSTG * 15360;  // 61440
    cudaFuncSetAttribute(mma_gemm, cudaFuncAttributeMaxDynamicSharedMemorySize, MMA_SMEM);
    cudaFuncSetAttribute(mma_gemm64, cudaFuncAttributeMaxDynamicSharedMemorySize, MMA_SMEM64);

    const int M = BB * TT;

    splitX<<<(M * HID_) / 256, 256>>>(X, XA2);                             // 1
    transW<<<dim3(96, 32), 256>>>(Wq, Wk, Wv, W2q);                        // 2
    transAB<<<8, 256>>>(Wa, Wb, W2q);                                      // 3
    mma_gemm<<<dim3(NQ / 128, 16), 256, MMA_SMEM>>>(XA2, W2q, qkv, NQ);    // 4 <- profiled
    transW<<<dim3(32, 32), 256>>>(Wo, Wo, Wo, W2o);                        // 5
    abpost<<<(M * NH) / 256, 256>>>(qkv, bb, A_log, dt_bias, beta, gdec);
    conv2_kernel<<<dim3(M, 2), 1024>>>(qkv, Wconv_q, Wconv_k, qn, kn);
    pass1_kernel<<<BB * NH * NCH, 256>>>(kn, qkv, gdec, beta);
    pass2b_kernel<<<BB * NH * 16, 256>>>();
    fused2_kernel<<<BB * NH * NCH2, 256>>>(kn, qn, qkv, gdec, beta, lambda_p, norm_w, onA2);
    mma_gemm64<<<dim3(HID_ / 128, M / 64), 256, MMA_SMEM64>>>(onA2, W2o, (float*)d_out, HID_);
}